// round 12
// baseline (speedup 1.0000x reference)
#include <cuda_runtime.h>
#include <cuda_fp16.h>
#include <math.h>
#include <stdint.h>

// ---------------------------------------------------------------------------
// Problem constants
// ---------------------------------------------------------------------------
#define BATCH   32
#define HIMG    56
#define WIMG    56
#define CDIM    384
#define LTOK    (HIMG*WIMG)          // 3136
#define NHEADS  12
#define HD      32
#define WS      7
#define NWIN_T  49
#define SHIFT   3
#define NWX     8
#define NWIN    64
#define BN      (BATCH*NWIN)         // 2048 windows
#define MTOK    (BN*NWIN_T)          // 100352 tokens
#define HID     1536

// ---------------------------------------------------------------------------
// Scratch (device globals)
// ---------------------------------------------------------------------------
__device__ __half g_qkv [(size_t)MTOK * 3 * CDIM];
__device__ float  g_proj[(size_t)MTOK * CDIM];
__device__ float  g_y   [(size_t)MTOK * CDIM];
__device__ __half g_win [(size_t)MTOK * CDIM];
__device__ __half g_att [(size_t)MTOK * CDIM];
__device__ __half g_h2  [(size_t)MTOK * CDIM];
__device__ __half g_mlp [(size_t)MTOK * HID];
// transposed weights Wt[N][K], fp16
__device__ __half g_wq[3*CDIM*CDIM];
__device__ __half g_wp[CDIM*CDIM];
__device__ __half g_w1[HID*CDIM];
__device__ __half g_w2[CDIM*HID];

// ---------------------------------------------------------------------------
// Helpers
// ---------------------------------------------------------------------------
static __device__ __forceinline__ uint32_t s2u(const void* p) {
    return (uint32_t)__cvta_generic_to_shared(p);
}
static __device__ __forceinline__ void ldm4(uint32_t& d0, uint32_t& d1, uint32_t& d2,
                                            uint32_t& d3, uint32_t a) {
    asm volatile("ldmatrix.sync.aligned.m8n8.x4.shared.b16 {%0,%1,%2,%3},[%4];"
                 : "=r"(d0), "=r"(d1), "=r"(d2), "=r"(d3) : "r"(a));
}
static __device__ __forceinline__ void mma_f16(float* c, const uint32_t* a, const uint32_t* b) {
    asm volatile("mma.sync.aligned.m16n8k16.row.col.f32.f16.f16.f32 "
                 "{%0,%1,%2,%3},{%4,%5,%6,%7},{%8,%9},{%0,%1,%2,%3};"
                 : "+f"(c[0]), "+f"(c[1]), "+f"(c[2]), "+f"(c[3])
                 : "r"(a[0]), "r"(a[1]), "r"(a[2]), "r"(a[3]), "r"(b[0]), "r"(b[1]));
}
static __device__ __forceinline__ void cpa16(uint32_t dst, const void* src) {
    asm volatile("cp.async.cg.shared.global [%0], [%1], 16;"
                 :: "r"(dst), "l"(src) : "memory");
}

// ---------------------------------------------------------------------------
// fp16 MMA GEMM: C[M,N] = A[M,K] @ B[N,K]^T, single pass, fp32 accumulate.
// 128x128 block tile, BK=32, 8 warps (2x4), warp tile 64x32.
// 64B smem rows (4 granules), swizzle g ^= (row>>1)&3.
// 4-stage cp.async (issue 3 ahead, wait_group 2), 2 CTAs/SM,
// one __syncthreads per chunk. B fragments for both k-steps hoisted.
// EPI 0: fp32 + bias | 1: bias+GELU -> fp16 | 2: bias+residual -> fp32
// EPI 3: bias -> fp16
// ---------------------------------------------------------------------------
#define TILE_B   (128*64)                 // 8192 bytes (128 rows x 64B)
#define STAGE_B  (2*TILE_B)               // A + B : 16384 bytes
#define NSTAGE   4
#define GEMM_SMEM (NSTAGE*STAGE_B)        // 65536 bytes

template <int EPI>
__global__ __launch_bounds__(256, 2)
void mma_gemm(const __half* __restrict__ A, const __half* __restrict__ B,
              const float* __restrict__ bias, const float* __restrict__ res,
              float* __restrict__ Cf, __half* __restrict__ Cm, int N, int K)
{
    extern __shared__ char sm[];
    const int tid  = threadIdx.x, lane = tid & 31, warp = tid >> 5;
    const int m0 = blockIdx.y * 128, n0 = blockIdx.x * 128;
    const int wm = (warp >> 2) * 64, wn = (warp & 3) * 32;

    // copy setup: thread owns row cr, granules g0 and g0+1 (16B = 8 halves each)
    const int cr = tid >> 1, g0 = (tid & 1) * 2;
    const __half* pA = A + (size_t)(m0 + cr) * K;
    const __half* pB = B + (size_t)(n0 + cr) * K;
    const uint32_t swc = ((uint32_t)cr >> 1) & 3;
    const uint32_t so0 = (uint32_t)cr * 64 + ((((uint32_t)g0    ) ^ swc) << 4);
    const uint32_t so1 = (uint32_t)cr * 64 + ((((uint32_t)g0 + 1) ^ swc) << 4);
    const uint32_t smb = s2u(sm);
    const int nch = K >> 5;

    auto issue_stage = [&](int i, int s) {
        int k0 = i << 5;
        uint32_t b = smb + (uint32_t)s * STAGE_B;
        cpa16(b + so0,          pA + k0 + g0 * 8);
        cpa16(b + so1,          pA + k0 + g0 * 8 + 8);
        cpa16(b + TILE_B + so0, pB + k0 + g0 * 8);
        cpa16(b + TILE_B + so1, pB + k0 + g0 * 8 + 8);
        asm volatile("cp.async.commit_group;" ::: "memory");
    };

    float acc[4][4][4];
    #pragma unroll
    for (int i = 0; i < 4; i++)
        #pragma unroll
        for (int j = 0; j < 4; j++)
            #pragma unroll
            for (int k = 0; k < 4; k++) acc[i][j][k] = 0.0f;

    // ldmatrix lane addressing
    const int tsel = lane >> 3, rlo = lane & 7;
    const uint32_t rA = (uint32_t)(wm + rlo + (tsel & 1) * 8);
    const uint32_t gA = (uint32_t)(tsel >> 1);
    const uint32_t rB = (uint32_t)(wn + rlo + (tsel >> 1) * 8);
    const uint32_t gB = (uint32_t)(tsel & 1);

    issue_stage(0, 0);
    if (nch > 1) issue_stage(1, 1);
    if (nch > 2) issue_stage(2, 2);

    int stage = 0;
    for (int i = 0; i < nch; i++) {
        int rem = nch - 1 - i;
        if (rem >= 2)      asm volatile("cp.async.wait_group 2;" ::: "memory");
        else if (rem == 1) asm volatile("cp.async.wait_group 1;" ::: "memory");
        else               asm volatile("cp.async.wait_group 0;" ::: "memory");
        __syncthreads();

        if (i + 3 < nch) {
            int s = stage + 3; if (s >= NSTAGE) s -= NSTAGE;
            issue_stage(i + 3, s);
        }

        const uint32_t sb = smb + (uint32_t)stage * STAGE_B;

        // hoist B fragments for both k-steps (overlaps kst1 LDSM with kst0 MMA)
        uint32_t bfr[2][4][2];
        #pragma unroll
        for (int kst = 0; kst < 2; kst++)
            #pragma unroll
            for (int p = 0; p < 2; p++) {
                uint32_t row = rB + p * 16;
                uint32_t sw  = (row >> 1) & 3;
                uint32_t ad  = sb + TILE_B + row * 64 + (((gB + kst*2u) ^ sw) << 4);
                ldm4(bfr[kst][2*p][0], bfr[kst][2*p][1],
                     bfr[kst][2*p+1][0], bfr[kst][2*p+1][1], ad);
            }
        #pragma unroll
        for (int kst = 0; kst < 2; kst++) {
            #pragma unroll
            for (int mf = 0; mf < 4; mf++) {
                uint32_t row = rA + mf * 16;
                uint32_t sw  = (row >> 1) & 3;
                uint32_t ad  = sb + row * 64 + (((gA + kst*2u) ^ sw) << 4);
                uint32_t afr[4];
                ldm4(afr[0], afr[1], afr[2], afr[3], ad);
                #pragma unroll
                for (int nf = 0; nf < 4; nf++)
                    mma_f16(acc[mf][nf], afr, bfr[kst][nf]);
            }
        }
        stage++; if (stage >= NSTAGE) stage = 0;
    }
    __syncthreads();

    // -- epilogue from accumulator fragments
    const int qr = lane >> 2, qc = (lane & 3) * 2;
    #pragma unroll
    for (int mf = 0; mf < 4; mf++) {
        int row = m0 + wm + mf * 16 + qr;
        #pragma unroll
        for (int nf = 0; nf < 4; nf++) {
            int col = n0 + wn + nf * 8 + qc;
            float b0 = bias[col], b1 = bias[col + 1];
            float v0 = acc[mf][nf][0] + b0, v1 = acc[mf][nf][1] + b1;
            float v2 = acc[mf][nf][2] + b0, v3 = acc[mf][nf][3] + b1;
            if (EPI == 0) {
                *(float2*)(Cf + (size_t)row * N + col)       = make_float2(v0, v1);
                *(float2*)(Cf + (size_t)(row + 8) * N + col) = make_float2(v2, v3);
            } else if (EPI == 1) {
                v0 = 0.5f * v0 * (1.0f + erff(v0 * 0.70710678118654752f));
                v1 = 0.5f * v1 * (1.0f + erff(v1 * 0.70710678118654752f));
                v2 = 0.5f * v2 * (1.0f + erff(v2 * 0.70710678118654752f));
                v3 = 0.5f * v3 * (1.0f + erff(v3 * 0.70710678118654752f));
                *(__half2*)(Cm + (size_t)row * N + col)       = __floats2half2_rn(v0, v1);
                *(__half2*)(Cm + (size_t)(row + 8) * N + col) = __floats2half2_rn(v2, v3);
            } else if (EPI == 2) {
                float2 r0v = *(const float2*)(res + (size_t)row * N + col);
                float2 r1v = *(const float2*)(res + (size_t)(row + 8) * N + col);
                *(float2*)(Cf + (size_t)row * N + col)       = make_float2(v0 + r0v.x, v1 + r0v.y);
                *(float2*)(Cf + (size_t)(row + 8) * N + col) = make_float2(v2 + r1v.x, v3 + r1v.y);
            } else {
                *(__half2*)(Cm + (size_t)row * N + col)       = __floats2half2_rn(v0, v1);
                *(__half2*)(Cm + (size_t)(row + 8) * N + col) = __floats2half2_rn(v2, v3);
            }
        }
    }
}

// ---------------------------------------------------------------------------
// Weight transpose + fp16 round: W[K][N] fp32 -> Wt[N][K] fp16
// ---------------------------------------------------------------------------
__global__ __launch_bounds__(256)
void wtrans_kernel(const float* __restrict__ W, __half* __restrict__ Wt, int K, int N)
{
    __shared__ float t[32][33];
    int tx = threadIdx.x & 31, ty = threadIdx.x >> 5;   // 32 x 8
    int kb = blockIdx.y * 32, nb = blockIdx.x * 32;
    #pragma unroll
    for (int j = ty; j < 32; j += 8)
        t[j][tx] = W[(size_t)(kb + j) * N + nb + tx];
    __syncthreads();
    #pragma unroll
    for (int j = ty; j < 32; j += 8)
        Wt[(size_t)(nb + j) * K + kb + tx] = __float2half_rn(t[tx][j]);
}

// ---------------------------------------------------------------------------
// LN1 + shift + window-partition gather -> fp16
// ---------------------------------------------------------------------------
__global__ __launch_bounds__(128)
void ln1_kernel(const float* __restrict__ x, const float* __restrict__ gam,
                const float* __restrict__ bet, __half* __restrict__ out)
{
    int tr = blockIdx.x;
    int bn = tr / NWIN_T;
    int n  = tr - bn * NWIN_T;
    int b  = bn / NWIN;
    int wi = bn - b * NWIN;
    int wy = wi / NWX, wx = wi - wy * NWX;
    int r  = n / WS,   cc = n - r * WS;
    int hs = (wy * WS + r  + SHIFT) % HIMG;
    int ws2= (wx * WS + cc + SHIFT) % WIMG;
    int src = b * LTOK + hs * WIMG + ws2;

    const float* xin = x + (size_t)src * CDIM;
    int tid = threadIdx.x;
    float v0 = xin[tid], v1 = xin[tid + 128], v2 = xin[tid + 256];
    float s  = v0 + v1 + v2;
    float ss = v0*v0 + v1*v1 + v2*v2;
    #pragma unroll
    for (int o = 16; o > 0; o >>= 1) {
        s  += __shfl_down_sync(0xffffffffu, s,  o);
        ss += __shfl_down_sync(0xffffffffu, ss, o);
    }
    __shared__ float red[8];
    __shared__ float mbv[2];
    int w = tid >> 5, l = tid & 31;
    if (l == 0) { red[w] = s; red[4 + w] = ss; }
    __syncthreads();
    if (tid == 0) {
        float S  = red[0] + red[1] + red[2] + red[3];
        float SS = red[4] + red[5] + red[6] + red[7];
        float mean = S * (1.0f / CDIM);
        float var  = SS * (1.0f / CDIM) - mean * mean;
        mbv[0] = mean; mbv[1] = rsqrtf(var + 1e-5f);
    }
    __syncthreads();
    float mean = mbv[0], rstd = mbv[1];
    __half* o = out + (size_t)tr * CDIM;
    o[tid]       = __float2half_rn((v0 - mean) * rstd * gam[tid]       + bet[tid]);
    o[tid + 128] = __float2half_rn((v1 - mean) * rstd * gam[tid + 128] + bet[tid + 128]);
    o[tid + 256] = __float2half_rn((v2 - mean) * rstd * gam[tid + 256] + bet[tid + 256]);
}

// ---------------------------------------------------------------------------
// Fused: window-reverse + roll + residual (y exact fp32), then LN2 -> fp16
// ---------------------------------------------------------------------------
__global__ __launch_bounds__(128)
void mergeln_kernel(const float* __restrict__ x, const float* __restrict__ proj,
                    const float* __restrict__ gam, const float* __restrict__ bet,
                    float* __restrict__ y, __half* __restrict__ out)
{
    int tr = blockIdx.x;
    int b = tr / LTOK, pos = tr - b * LTOK;
    int i = pos / WIMG, j = pos - i * WIMG;
    int ii = (i + HIMG - SHIFT) % HIMG;
    int jj = (j + WIMG - SHIFT) % WIMG;
    int wr = (b * NWIN + (ii / WS) * NWX + (jj / WS)) * NWIN_T + (ii % WS) * WS + (jj % WS);

    const float* xp = x    + (size_t)tr * CDIM;
    const float* pp = proj + (size_t)wr * CDIM;
    int tid = threadIdx.x;
    float v0 = xp[tid]       + pp[tid];
    float v1 = xp[tid + 128] + pp[tid + 128];
    float v2 = xp[tid + 256] + pp[tid + 256];

    float* yp = y + (size_t)tr * CDIM;
    yp[tid] = v0; yp[tid + 128] = v1; yp[tid + 256] = v2;

    float s  = v0 + v1 + v2;
    float ss = v0*v0 + v1*v1 + v2*v2;
    #pragma unroll
    for (int o = 16; o > 0; o >>= 1) {
        s  += __shfl_down_sync(0xffffffffu, s,  o);
        ss += __shfl_down_sync(0xffffffffu, ss, o);
    }
    __shared__ float red[8];
    __shared__ float mbv[2];
    int w = tid >> 5, l = tid & 31;
    if (l == 0) { red[w] = s; red[4 + w] = ss; }
    __syncthreads();
    if (tid == 0) {
        float S  = red[0] + red[1] + red[2] + red[3];
        float SS = red[4] + red[5] + red[6] + red[7];
        float mean = S * (1.0f / CDIM);
        float var  = SS * (1.0f / CDIM) - mean * mean;
        mbv[0] = mean; mbv[1] = rsqrtf(var + 1e-5f);
    }
    __syncthreads();
    float mean = mbv[0], rstd = mbv[1];
    __half* o = out + (size_t)tr * CDIM;
    o[tid]       = __float2half_rn((v0 - mean) * rstd * gam[tid]       + bet[tid]);
    o[tid + 128] = __float2half_rn((v1 - mean) * rstd * gam[tid + 128] + bet[tid + 128]);
    o[tid + 256] = __float2half_rn((v2 - mean) * rstd * gam[tid + 256] + bet[tid + 256]);
}

// ---------------------------------------------------------------------------
// Windowed attention: one block (64 thr) per (window, head).
// qkv is fp16; converted to fp32 in smem. Thread n keeps Q/output rows in
// registers; K/V rows via broadcast LDS.128. Output fp16.
// ---------------------------------------------------------------------------
#define SST 50   // padded logits stride
__global__ __launch_bounds__(64)
void attn_kernel(const __half* __restrict__ qkv, const float* __restrict__ mask,
                 const float* __restrict__ rpb, __half* __restrict__ outp)
{
    __shared__ float Qs[NWIN_T * 32];
    __shared__ float Ks[NWIN_T * 32];
    __shared__ float Vs[NWIN_T * 32];
    __shared__ float Ss[NWIN_T * SST];

    int bn = blockIdx.x, h = blockIdx.y, tid = threadIdx.x;
    const float scale = 0.1767766952966369f;   // 32^-0.5

    size_t basep = (size_t)bn * NWIN_T * (3 * CDIM) + h * HD;
    for (int idx = tid; idx < NWIN_T * 4; idx += 64) {
        int n = idx >> 2, q = (idx & 3) * 8;       // 8 halves per step
        const __half* rowp = qkv + basep + (size_t)n * (3 * CDIM);
        uint4 qr = *(const uint4*)(rowp + q);
        uint4 kr = *(const uint4*)(rowp + CDIM + q);
        uint4 vr = *(const uint4*)(rowp + 2 * CDIM + q);
        const __half2* qh = (const __half2*)&qr;
        const __half2* kh = (const __half2*)&kr;
        const __half2* vh = (const __half2*)&vr;
        #pragma unroll
        for (int j = 0; j < 4; j++) {
            float2 f;
            f = __half22float2(qh[j]);
            Qs[n * 32 + q + 2*j]     = f.x * scale;
            Qs[n * 32 + q + 2*j + 1] = f.y * scale;
            f = __half22float2(kh[j]);
            Ks[n * 32 + q + 2*j]     = f.x;
            Ks[n * 32 + q + 2*j + 1] = f.y;
            f = __half22float2(vh[j]);
            Vs[n * 32 + q + 2*j]     = f.x;
            Vs[n * 32 + q + 2*j + 1] = f.y;
        }
    }
    __syncthreads();

    if (tid < NWIN_T) {
        const int n = tid;
        const float* mw = mask + (bn & (NWIN - 1)) * (NWIN_T * NWIN_T) + n * NWIN_T;
        const int r1 = n / WS, c1 = n - r1 * WS;

        float q[32];
        #pragma unroll
        for (int i = 0; i < 8; i++) {
            float4 v = *(const float4*)&Qs[n * 32 + i * 4];
            q[i*4+0] = v.x; q[i*4+1] = v.y; q[i*4+2] = v.z; q[i*4+3] = v.w;
        }

        for (int m = 0; m < NWIN_T; m++) {
            float acc = 0.0f;
            #pragma unroll
            for (int i = 0; i < 8; i++) {
                float4 kv = *(const float4*)&Ks[m * 32 + i * 4];
                acc += q[i*4+0]*kv.x + q[i*4+1]*kv.y + q[i*4+2]*kv.z + q[i*4+3]*kv.w;
            }
            int r2 = m / WS, c2 = m - r2 * WS;
            int rel = (r1 - r2 + WS - 1) * (2 * WS - 1) + (c1 - c2 + WS - 1);
            Ss[n * SST + m] = acc + rpb[rel * NHEADS + h] + mw[m];
        }

        float mx = -1e30f;
        for (int m = 0; m < NWIN_T; m++) mx = fmaxf(mx, Ss[n * SST + m]);
        float sum = 0.0f;
        for (int m = 0; m < NWIN_T; m++) {
            float e = __expf(Ss[n * SST + m] - mx);
            Ss[n * SST + m] = e; sum += e;
        }
        float inv = 1.0f / sum;

        float acc[32];
        #pragma unroll
        for (int i = 0; i < 32; i++) acc[i] = 0.0f;
        for (int m = 0; m < NWIN_T; m++) {
            float p = Ss[n * SST + m];
            #pragma unroll
            for (int i = 0; i < 8; i++) {
                float4 vv = *(const float4*)&Vs[m * 32 + i * 4];
                acc[i*4+0] += p * vv.x; acc[i*4+1] += p * vv.y;
                acc[i*4+2] += p * vv.z; acc[i*4+3] += p * vv.w;
            }
        }
        __half* op = outp + (size_t)(bn * NWIN_T + n) * CDIM + h * HD;
        #pragma unroll
        for (int i = 0; i < 16; i++)
            *(__half2*)(op + 2*i) = __floats2half2_rn(acc[2*i] * inv, acc[2*i+1] * inv);
    }
}

// ---------------------------------------------------------------------------
// Launch
// ---------------------------------------------------------------------------
extern "C" void kernel_launch(void* const* d_in, const int* in_sizes, int n_in,
                              void* d_out, int out_size)
{
    const float* x        = (const float*)d_in[0];
    const float* attnmask = (const float*)d_in[1];
    const float* norm1_g  = (const float*)d_in[2];
    const float* norm1_b  = (const float*)d_in[3];
    const float* qkv_w    = (const float*)d_in[4];
    const float* qkv_b    = (const float*)d_in[5];
    const float* rpb      = (const float*)d_in[6];
    const float* proj_w   = (const float*)d_in[7];
    const float* proj_b   = (const float*)d_in[8];
    const float* norm2_g  = (const float*)d_in[9];
    const float* norm2_b  = (const float*)d_in[10];
    const float* fc1_w    = (const float*)d_in[11];
    const float* fc1_b    = (const float*)d_in[12];
    const float* fc2_w    = (const float*)d_in[13];
    const float* fc2_b    = (const float*)d_in[14];
    (void)in_sizes; (void)n_in; (void)out_size;

    float *projb, *y;
    __half *qkvbuf, *win, *att, *h2, *mlp, *wq, *wp, *w1, *w2;
    cudaGetSymbolAddress((void**)&qkvbuf, g_qkv);
    cudaGetSymbolAddress((void**)&projb,  g_proj);
    cudaGetSymbolAddress((void**)&y,      g_y);
    cudaGetSymbolAddress((void**)&win,    g_win);
    cudaGetSymbolAddress((void**)&att,    g_att);
    cudaGetSymbolAddress((void**)&h2,     g_h2);
    cudaGetSymbolAddress((void**)&mlp,    g_mlp);
    cudaGetSymbolAddress((void**)&wq,     g_wq);
    cudaGetSymbolAddress((void**)&wp,     g_wp);
    cudaGetSymbolAddress((void**)&w1,     g_w1);
    cudaGetSymbolAddress((void**)&w2,     g_w2);

    cudaFuncSetAttribute(mma_gemm<1>, cudaFuncAttributeMaxDynamicSharedMemorySize, GEMM_SMEM);
    cudaFuncSetAttribute(mma_gemm<0>, cudaFuncAttributeMaxDynamicSharedMemorySize, GEMM_SMEM);
    cudaFuncSetAttribute(mma_gemm<2>, cudaFuncAttributeMaxDynamicSharedMemorySize, GEMM_SMEM);
    cudaFuncSetAttribute(mma_gemm<3>, cudaFuncAttributeMaxDynamicSharedMemorySize, GEMM_SMEM);

    // 0. weight transpose + fp16 round
    wtrans_kernel<<<dim3(3*CDIM/32, CDIM/32), 256>>>(qkv_w,  wq, CDIM, 3*CDIM);
    wtrans_kernel<<<dim3(CDIM/32,   CDIM/32), 256>>>(proj_w, wp, CDIM, CDIM);
    wtrans_kernel<<<dim3(HID/32,    CDIM/32), 256>>>(fc1_w,  w1, CDIM, HID);
    wtrans_kernel<<<dim3(CDIM/32,   HID/32),  256>>>(fc2_w,  w2, HID,  CDIM);

    // 1. LN1 + shift + window partition (fp16)
    ln1_kernel<<<MTOK, 128>>>(x, norm1_g, norm1_b, win);

    // 2. QKV GEMM (100352 x 384) @ (384 x 1152) -> fp16
    mma_gemm<3><<<dim3(9, MTOK/128), 256, GEMM_SMEM>>>(
        win, wq, qkv_b, nullptr, nullptr, qkvbuf, 3*CDIM, CDIM);

    // 3. Windowed attention (fp16 in, fp16 out)
    attn_kernel<<<dim3(BN, NHEADS), 64>>>(qkvbuf, attnmask, rpb, att);

    // 4. proj GEMM -> fp32
    mma_gemm<0><<<dim3(3, MTOK/128), 256, GEMM_SMEM>>>(
        att, wp, proj_b, nullptr, projb, nullptr, CDIM, CDIM);

    // 5+6. reverse + roll + residual + LN2 (fused)
    mergeln_kernel<<<MTOK, 128>>>(x, projb, norm2_g, norm2_b, y, h2);

    // 7. fc1 + GELU (fp16 out)
    mma_gemm<1><<<dim3(12, MTOK/128), 256, GEMM_SMEM>>>(
        h2, w1, fc1_b, nullptr, nullptr, mlp, HID, CDIM);

    // 8. fc2 + residual -> d_out
    mma_gemm<2><<<dim3(3, MTOK/128), 256, GEMM_SMEM>>>(
        mlp, w2, fc2_b, y, (float*)d_out, nullptr, CDIM, HID);
}

// round 13
// speedup vs baseline: 1.0359x; 1.0359x over previous
#include <cuda_runtime.h>
#include <cuda_fp16.h>
#include <math.h>
#include <stdint.h>

// ---------------------------------------------------------------------------
// Problem constants
// ---------------------------------------------------------------------------
#define BATCH   32
#define HIMG    56
#define WIMG    56
#define CDIM    384
#define LTOK    (HIMG*WIMG)          // 3136
#define NHEADS  12
#define HD      32
#define WS      7
#define NWIN_T  49
#define SHIFT   3
#define NWX     8
#define NWIN    64
#define BN      (BATCH*NWIN)         // 2048 windows
#define MTOK    (BN*NWIN_T)          // 100352 tokens
#define HID     1536

// ---------------------------------------------------------------------------
// Scratch (device globals)
// ---------------------------------------------------------------------------
__device__ __half g_qkv [(size_t)MTOK * 3 * CDIM];
__device__ float  g_proj[(size_t)MTOK * CDIM];
__device__ float  g_y   [(size_t)MTOK * CDIM];
__device__ __half g_win [(size_t)MTOK * CDIM];
__device__ __half g_att [(size_t)MTOK * CDIM];
__device__ __half g_h2  [(size_t)MTOK * CDIM];
__device__ __half g_mlp [(size_t)MTOK * HID];
// transposed weights Wt[N][K], fp16
__device__ __half g_wq[3*CDIM*CDIM];
__device__ __half g_wp[CDIM*CDIM];
__device__ __half g_w1[HID*CDIM];
__device__ __half g_w2[CDIM*HID];

// ---------------------------------------------------------------------------
// Helpers
// ---------------------------------------------------------------------------
static __device__ __forceinline__ uint32_t s2u(const void* p) {
    return (uint32_t)__cvta_generic_to_shared(p);
}
static __device__ __forceinline__ void ldm4(uint32_t& d0, uint32_t& d1, uint32_t& d2,
                                            uint32_t& d3, uint32_t a) {
    asm volatile("ldmatrix.sync.aligned.m8n8.x4.shared.b16 {%0,%1,%2,%3},[%4];"
                 : "=r"(d0), "=r"(d1), "=r"(d2), "=r"(d3) : "r"(a));
}
static __device__ __forceinline__ void mma_f16(float* c, const uint32_t* a, const uint32_t* b) {
    asm volatile("mma.sync.aligned.m16n8k16.row.col.f32.f16.f16.f32 "
                 "{%0,%1,%2,%3},{%4,%5,%6,%7},{%8,%9},{%0,%1,%2,%3};"
                 : "+f"(c[0]), "+f"(c[1]), "+f"(c[2]), "+f"(c[3])
                 : "r"(a[0]), "r"(a[1]), "r"(a[2]), "r"(a[3]), "r"(b[0]), "r"(b[1]));
}
static __device__ __forceinline__ void cpa16(uint32_t dst, const void* src) {
    asm volatile("cp.async.cg.shared.global [%0], [%1], 16;"
                 :: "r"(dst), "l"(src) : "memory");
}

// ---------------------------------------------------------------------------
// fp16 MMA GEMM: C[M,N] = A[M,K] @ B[N,K]^T, single pass, fp32 accumulate.
// 128x128 block tile, BK=64, 8 warps (2x4), warp tile 64x32.
// 128B smem rows (8 granules), swizzle g ^= row&7 (conflict-free).
// 3-stage cp.async (issue 2 ahead), 2 CTAs/SM, one __syncthreads per chunk.
// EPI 0: fp32 + bias | 1: bias+GELU -> fp16 | 2: bias+residual -> fp32
// EPI 3: bias -> fp16
// ---------------------------------------------------------------------------
#define TILE_B   (128*128)                // 16384 bytes (128 rows x 128B = 64 halves)
#define STAGE_B  (2*TILE_B)               // A + B : 32768 bytes
#define NSTAGE   3
#define GEMM_SMEM (NSTAGE*STAGE_B)        // 98304 bytes

template <int EPI>
__global__ __launch_bounds__(256, 2)
void mma_gemm(const __half* __restrict__ A, const __half* __restrict__ B,
              const float* __restrict__ bias, const float* __restrict__ res,
              float* __restrict__ Cf, __half* __restrict__ Cm, int N, int K)
{
    extern __shared__ char sm[];
    const int tid  = threadIdx.x, lane = tid & 31, warp = tid >> 5;
    const int m0 = blockIdx.y * 128, n0 = blockIdx.x * 128;
    const int wm = (warp >> 2) * 64, wn = (warp & 3) * 32;

    // copy setup: 2 threads per row; thread owns row cr, granules g0..g0+3
    const int cr = tid >> 1, g0 = (tid & 1) * 4;
    const __half* pA = A + (size_t)(m0 + cr) * K;
    const __half* pB = B + (size_t)(n0 + cr) * K;
    const uint32_t swc = (uint32_t)cr & 7;
    uint32_t so[4];
    #pragma unroll
    for (int j = 0; j < 4; j++)
        so[j] = (uint32_t)cr * 128 + ((((uint32_t)(g0 + j)) ^ swc) << 4);
    const uint32_t smb = s2u(sm);
    const int nch = K >> 6;

    auto issue_stage = [&](int i, int s) {
        int k0 = i << 6;
        uint32_t b = smb + (uint32_t)s * STAGE_B;
        #pragma unroll
        for (int j = 0; j < 4; j++) {
            cpa16(b + so[j],          pA + k0 + (g0 + j) * 8);
            cpa16(b + TILE_B + so[j], pB + k0 + (g0 + j) * 8);
        }
        asm volatile("cp.async.commit_group;" ::: "memory");
    };

    float acc[4][4][4];
    #pragma unroll
    for (int i = 0; i < 4; i++)
        #pragma unroll
        for (int j = 0; j < 4; j++)
            #pragma unroll
            for (int k = 0; k < 4; k++) acc[i][j][k] = 0.0f;

    // ldmatrix lane addressing: row&7 == rlo for every fragment tile
    const int tsel = lane >> 3, rlo = lane & 7;
    const uint32_t rA = (uint32_t)(wm + rlo + (tsel & 1) * 8);
    const uint32_t gA = (uint32_t)(tsel >> 1);
    const uint32_t rB = (uint32_t)(wn + rlo + (tsel >> 1) * 8);
    const uint32_t gB = (uint32_t)(tsel & 1);

    issue_stage(0, 0);
    if (nch > 1) issue_stage(1, 1);

    int stage = 0;
    for (int i = 0; i < nch; i++) {
        if (i + 1 < nch) asm volatile("cp.async.wait_group 1;" ::: "memory");
        else             asm volatile("cp.async.wait_group 0;" ::: "memory");
        __syncthreads();

        if (i + 2 < nch) {
            int s = stage + 2; if (s >= NSTAGE) s -= NSTAGE;
            issue_stage(i + 2, s);
        }

        const uint32_t sb = smb + (uint32_t)stage * STAGE_B;
        #pragma unroll
        for (int kst = 0; kst < 4; kst++) {
            uint32_t bfr[4][2];
            #pragma unroll
            for (int p = 0; p < 2; p++) {
                uint32_t row = rB + p * 16;
                uint32_t ad  = sb + TILE_B + row * 128 + (((gB + kst*2u) ^ (uint32_t)rlo) << 4);
                ldm4(bfr[2*p][0], bfr[2*p][1], bfr[2*p+1][0], bfr[2*p+1][1], ad);
            }
            #pragma unroll
            for (int mf = 0; mf < 4; mf++) {
                uint32_t row = rA + mf * 16;
                uint32_t ad  = sb + row * 128 + (((gA + kst*2u) ^ (uint32_t)rlo) << 4);
                uint32_t afr[4];
                ldm4(afr[0], afr[1], afr[2], afr[3], ad);
                #pragma unroll
                for (int nf = 0; nf < 4; nf++)
                    mma_f16(acc[mf][nf], afr, bfr[nf]);
            }
        }
        stage++; if (stage >= NSTAGE) stage = 0;
    }
    __syncthreads();

    // -- epilogue from accumulator fragments
    const int qr = lane >> 2, qc = (lane & 3) * 2;
    #pragma unroll
    for (int mf = 0; mf < 4; mf++) {
        int row = m0 + wm + mf * 16 + qr;
        #pragma unroll
        for (int nf = 0; nf < 4; nf++) {
            int col = n0 + wn + nf * 8 + qc;
            float b0 = bias[col], b1 = bias[col + 1];
            float v0 = acc[mf][nf][0] + b0, v1 = acc[mf][nf][1] + b1;
            float v2 = acc[mf][nf][2] + b0, v3 = acc[mf][nf][3] + b1;
            if (EPI == 0) {
                *(float2*)(Cf + (size_t)row * N + col)       = make_float2(v0, v1);
                *(float2*)(Cf + (size_t)(row + 8) * N + col) = make_float2(v2, v3);
            } else if (EPI == 1) {
                v0 = 0.5f * v0 * (1.0f + erff(v0 * 0.70710678118654752f));
                v1 = 0.5f * v1 * (1.0f + erff(v1 * 0.70710678118654752f));
                v2 = 0.5f * v2 * (1.0f + erff(v2 * 0.70710678118654752f));
                v3 = 0.5f * v3 * (1.0f + erff(v3 * 0.70710678118654752f));
                *(__half2*)(Cm + (size_t)row * N + col)       = __floats2half2_rn(v0, v1);
                *(__half2*)(Cm + (size_t)(row + 8) * N + col) = __floats2half2_rn(v2, v3);
            } else if (EPI == 2) {
                float2 r0v = *(const float2*)(res + (size_t)row * N + col);
                float2 r1v = *(const float2*)(res + (size_t)(row + 8) * N + col);
                *(float2*)(Cf + (size_t)row * N + col)       = make_float2(v0 + r0v.x, v1 + r0v.y);
                *(float2*)(Cf + (size_t)(row + 8) * N + col) = make_float2(v2 + r1v.x, v3 + r1v.y);
            } else {
                *(__half2*)(Cm + (size_t)row * N + col)       = __floats2half2_rn(v0, v1);
                *(__half2*)(Cm + (size_t)(row + 8) * N + col) = __floats2half2_rn(v2, v3);
            }
        }
    }
}

// ---------------------------------------------------------------------------
// Weight transpose + fp16 round: W[K][N] fp32 -> Wt[N][K] fp16
// ---------------------------------------------------------------------------
__global__ __launch_bounds__(256)
void wtrans_kernel(const float* __restrict__ W, __half* __restrict__ Wt, int K, int N)
{
    __shared__ float t[32][33];
    int tx = threadIdx.x & 31, ty = threadIdx.x >> 5;   // 32 x 8
    int kb = blockIdx.y * 32, nb = blockIdx.x * 32;
    #pragma unroll
    for (int j = ty; j < 32; j += 8)
        t[j][tx] = W[(size_t)(kb + j) * N + nb + tx];
    __syncthreads();
    #pragma unroll
    for (int j = ty; j < 32; j += 8)
        Wt[(size_t)(nb + j) * K + kb + tx] = __float2half_rn(t[tx][j]);
}

// ---------------------------------------------------------------------------
// LN1 + shift + window-partition gather -> fp16
// ---------------------------------------------------------------------------
__global__ __launch_bounds__(128)
void ln1_kernel(const float* __restrict__ x, const float* __restrict__ gam,
                const float* __restrict__ bet, __half* __restrict__ out)
{
    int tr = blockIdx.x;
    int bn = tr / NWIN_T;
    int n  = tr - bn * NWIN_T;
    int b  = bn / NWIN;
    int wi = bn - b * NWIN;
    int wy = wi / NWX, wx = wi - wy * NWX;
    int r  = n / WS,   cc = n - r * WS;
    int hs = (wy * WS + r  + SHIFT) % HIMG;
    int ws2= (wx * WS + cc + SHIFT) % WIMG;
    int src = b * LTOK + hs * WIMG + ws2;

    const float* xin = x + (size_t)src * CDIM;
    int tid = threadIdx.x;
    float v0 = xin[tid], v1 = xin[tid + 128], v2 = xin[tid + 256];
    float s  = v0 + v1 + v2;
    float ss = v0*v0 + v1*v1 + v2*v2;
    #pragma unroll
    for (int o = 16; o > 0; o >>= 1) {
        s  += __shfl_down_sync(0xffffffffu, s,  o);
        ss += __shfl_down_sync(0xffffffffu, ss, o);
    }
    __shared__ float red[8];
    __shared__ float mbv[2];
    int w = tid >> 5, l = tid & 31;
    if (l == 0) { red[w] = s; red[4 + w] = ss; }
    __syncthreads();
    if (tid == 0) {
        float S  = red[0] + red[1] + red[2] + red[3];
        float SS = red[4] + red[5] + red[6] + red[7];
        float mean = S * (1.0f / CDIM);
        float var  = SS * (1.0f / CDIM) - mean * mean;
        mbv[0] = mean; mbv[1] = rsqrtf(var + 1e-5f);
    }
    __syncthreads();
    float mean = mbv[0], rstd = mbv[1];
    __half* o = out + (size_t)tr * CDIM;
    o[tid]       = __float2half_rn((v0 - mean) * rstd * gam[tid]       + bet[tid]);
    o[tid + 128] = __float2half_rn((v1 - mean) * rstd * gam[tid + 128] + bet[tid + 128]);
    o[tid + 256] = __float2half_rn((v2 - mean) * rstd * gam[tid + 256] + bet[tid + 256]);
}

// ---------------------------------------------------------------------------
// Fused: window-reverse + roll + residual (y exact fp32), then LN2 -> fp16
// ---------------------------------------------------------------------------
__global__ __launch_bounds__(128)
void mergeln_kernel(const float* __restrict__ x, const float* __restrict__ proj,
                    const float* __restrict__ gam, const float* __restrict__ bet,
                    float* __restrict__ y, __half* __restrict__ out)
{
    int tr = blockIdx.x;
    int b = tr / LTOK, pos = tr - b * LTOK;
    int i = pos / WIMG, j = pos - i * WIMG;
    int ii = (i + HIMG - SHIFT) % HIMG;
    int jj = (j + WIMG - SHIFT) % WIMG;
    int wr = (b * NWIN + (ii / WS) * NWX + (jj / WS)) * NWIN_T + (ii % WS) * WS + (jj % WS);

    const float* xp = x    + (size_t)tr * CDIM;
    const float* pp = proj + (size_t)wr * CDIM;
    int tid = threadIdx.x;
    float v0 = xp[tid]       + pp[tid];
    float v1 = xp[tid + 128] + pp[tid + 128];
    float v2 = xp[tid + 256] + pp[tid + 256];

    float* yp = y + (size_t)tr * CDIM;
    yp[tid] = v0; yp[tid + 128] = v1; yp[tid + 256] = v2;

    float s  = v0 + v1 + v2;
    float ss = v0*v0 + v1*v1 + v2*v2;
    #pragma unroll
    for (int o = 16; o > 0; o >>= 1) {
        s  += __shfl_down_sync(0xffffffffu, s,  o);
        ss += __shfl_down_sync(0xffffffffu, ss, o);
    }
    __shared__ float red[8];
    __shared__ float mbv[2];
    int w = tid >> 5, l = tid & 31;
    if (l == 0) { red[w] = s; red[4 + w] = ss; }
    __syncthreads();
    if (tid == 0) {
        float S  = red[0] + red[1] + red[2] + red[3];
        float SS = red[4] + red[5] + red[6] + red[7];
        float mean = S * (1.0f / CDIM);
        float var  = SS * (1.0f / CDIM) - mean * mean;
        mbv[0] = mean; mbv[1] = rsqrtf(var + 1e-5f);
    }
    __syncthreads();
    float mean = mbv[0], rstd = mbv[1];
    __half* o = out + (size_t)tr * CDIM;
    o[tid]       = __float2half_rn((v0 - mean) * rstd * gam[tid]       + bet[tid]);
    o[tid + 128] = __float2half_rn((v1 - mean) * rstd * gam[tid + 128] + bet[tid + 128]);
    o[tid + 256] = __float2half_rn((v2 - mean) * rstd * gam[tid + 256] + bet[tid + 256]);
}

// ---------------------------------------------------------------------------
// Windowed attention: one block (64 thr) per (window, head).
// QK and PV phases split rows into 2 half-units -> 98 units over 64 threads
// (full packing); softmax (exp; MUFU-bound) stays 1 thread per row.
// ---------------------------------------------------------------------------
#define SST 50   // padded logits stride
__global__ __launch_bounds__(64)
void attn_kernel(const __half* __restrict__ qkv, const float* __restrict__ mask,
                 const float* __restrict__ rpb, __half* __restrict__ outp)
{
    __shared__ float Qs[NWIN_T * 32];
    __shared__ float Ks[NWIN_T * 32];
    __shared__ float Vs[NWIN_T * 32];
    __shared__ float Ss[NWIN_T * SST];

    int bn = blockIdx.x, h = blockIdx.y, tid = threadIdx.x;
    const float scale = 0.1767766952966369f;   // 32^-0.5

    size_t basep = (size_t)bn * NWIN_T * (3 * CDIM) + h * HD;
    for (int idx = tid; idx < NWIN_T * 4; idx += 64) {
        int n = idx >> 2, q = (idx & 3) * 8;       // 8 halves per step
        const __half* rowp = qkv + basep + (size_t)n * (3 * CDIM);
        uint4 qr = *(const uint4*)(rowp + q);
        uint4 kr = *(const uint4*)(rowp + CDIM + q);
        uint4 vr = *(const uint4*)(rowp + 2 * CDIM + q);
        const __half2* qh = (const __half2*)&qr;
        const __half2* kh = (const __half2*)&kr;
        const __half2* vh = (const __half2*)&vr;
        #pragma unroll
        for (int j = 0; j < 4; j++) {
            float2 f;
            f = __half22float2(qh[j]);
            Qs[n * 32 + q + 2*j]     = f.x * scale;
            Qs[n * 32 + q + 2*j + 1] = f.y * scale;
            f = __half22float2(kh[j]);
            Ks[n * 32 + q + 2*j]     = f.x;
            Ks[n * 32 + q + 2*j + 1] = f.y;
            f = __half22float2(vh[j]);
            Vs[n * 32 + q + 2*j]     = f.x;
            Vs[n * 32 + q + 2*j + 1] = f.y;
        }
    }
    __syncthreads();

    const float* mwb = mask + (bn & (NWIN - 1)) * (NWIN_T * NWIN_T);

    // --- QK phase: 98 units (row, m-half), full 64-thread packing
    for (int u = tid; u < 2 * NWIN_T; u += 64) {
        int n   = u >> 1;
        int seg = u & 1;
        int mlo = seg ? 25 : 0;
        int mhi = seg ? NWIN_T : 25;
        const int r1 = n / WS, c1 = n - r1 * WS;
        float q[32];
        #pragma unroll
        for (int i = 0; i < 8; i++) {
            float4 v = *(const float4*)&Qs[n * 32 + i * 4];
            q[i*4+0] = v.x; q[i*4+1] = v.y; q[i*4+2] = v.z; q[i*4+3] = v.w;
        }
        for (int m = mlo; m < mhi; m++) {
            float acc = 0.0f;
            #pragma unroll
            for (int i = 0; i < 8; i++) {
                float4 kv = *(const float4*)&Ks[m * 32 + i * 4];
                acc += q[i*4+0]*kv.x + q[i*4+1]*kv.y + q[i*4+2]*kv.z + q[i*4+3]*kv.w;
            }
            int r2 = m / WS, c2 = m - r2 * WS;
            int rel = (r1 - r2 + WS - 1) * (2 * WS - 1) + (c1 - c2 + WS - 1);
            Ss[n * SST + m] = acc + rpb[rel * NHEADS + h] + mwb[n * NWIN_T + m];
        }
    }
    __syncthreads();

    // --- softmax: one thread per row (exp is MUFU-bound)
    if (tid < NWIN_T) {
        const int n = tid;
        float mx = -1e30f;
        for (int m = 0; m < NWIN_T; m++) mx = fmaxf(mx, Ss[n * SST + m]);
        float sum = 0.0f;
        for (int m = 0; m < NWIN_T; m++) {
            float e = __expf(Ss[n * SST + m] - mx);
            Ss[n * SST + m] = e; sum += e;
        }
        float inv = 1.0f / sum;
        Ss[n * SST + NWIN_T] = inv;   // stash per-row 1/sum (col 49 < SST)
    }
    __syncthreads();

    // --- PV phase: 98 units (row, 16-channel half), full packing
    for (int u = tid; u < 2 * NWIN_T; u += 64) {
        int n   = u >> 1;
        int ch0 = (u & 1) * 16;
        float inv = Ss[n * SST + NWIN_T];
        float acc[16];
        #pragma unroll
        for (int i = 0; i < 16; i++) acc[i] = 0.0f;
        for (int m = 0; m < NWIN_T; m++) {
            float p = Ss[n * SST + m];
            #pragma unroll
            for (int i = 0; i < 4; i++) {
                float4 vv = *(const float4*)&Vs[m * 32 + ch0 + i * 4];
                acc[i*4+0] += p * vv.x; acc[i*4+1] += p * vv.y;
                acc[i*4+2] += p * vv.z; acc[i*4+3] += p * vv.w;
            }
        }
        __half* op = outp + (size_t)(bn * NWIN_T + n) * CDIM + h * HD + ch0;
        #pragma unroll
        for (int i = 0; i < 8; i++)
            *(__half2*)(op + 2*i) = __floats2half2_rn(acc[2*i] * inv, acc[2*i+1] * inv);
    }
}

// ---------------------------------------------------------------------------
// Launch
// ---------------------------------------------------------------------------
extern "C" void kernel_launch(void* const* d_in, const int* in_sizes, int n_in,
                              void* d_out, int out_size)
{
    const float* x        = (const float*)d_in[0];
    const float* attnmask = (const float*)d_in[1];
    const float* norm1_g  = (const float*)d_in[2];
    const float* norm1_b  = (const float*)d_in[3];
    const float* qkv_w    = (const float*)d_in[4];
    const float* qkv_b    = (const float*)d_in[5];
    const float* rpb      = (const float*)d_in[6];
    const float* proj_w   = (const float*)d_in[7];
    const float* proj_b   = (const float*)d_in[8];
    const float* norm2_g  = (const float*)d_in[9];
    const float* norm2_b  = (const float*)d_in[10];
    const float* fc1_w    = (const float*)d_in[11];
    const float* fc1_b    = (const float*)d_in[12];
    const float* fc2_w    = (const float*)d_in[13];
    const float* fc2_b    = (const float*)d_in[14];
    (void)in_sizes; (void)n_in; (void)out_size;

    float *projb, *y;
    __half *qkvbuf, *win, *att, *h2, *mlp, *wq, *wp, *w1, *w2;
    cudaGetSymbolAddress((void**)&qkvbuf, g_qkv);
    cudaGetSymbolAddress((void**)&projb,  g_proj);
    cudaGetSymbolAddress((void**)&y,      g_y);
    cudaGetSymbolAddress((void**)&win,    g_win);
    cudaGetSymbolAddress((void**)&att,    g_att);
    cudaGetSymbolAddress((void**)&h2,     g_h2);
    cudaGetSymbolAddress((void**)&mlp,    g_mlp);
    cudaGetSymbolAddress((void**)&wq,     g_wq);
    cudaGetSymbolAddress((void**)&wp,     g_wp);
    cudaGetSymbolAddress((void**)&w1,     g_w1);
    cudaGetSymbolAddress((void**)&w2,     g_w2);

    cudaFuncSetAttribute(mma_gemm<0>, cudaFuncAttributeMaxDynamicSharedMemorySize, GEMM_SMEM);
    cudaFuncSetAttribute(mma_gemm<1>, cudaFuncAttributeMaxDynamicSharedMemorySize, GEMM_SMEM);
    cudaFuncSetAttribute(mma_gemm<2>, cudaFuncAttributeMaxDynamicSharedMemorySize, GEMM_SMEM);
    cudaFuncSetAttribute(mma_gemm<3>, cudaFuncAttributeMaxDynamicSharedMemorySize, GEMM_SMEM);

    // 0. weight transpose + fp16 round
    wtrans_kernel<<<dim3(3*CDIM/32, CDIM/32), 256>>>(qkv_w,  wq, CDIM, 3*CDIM);
    wtrans_kernel<<<dim3(CDIM/32,   CDIM/32), 256>>>(proj_w, wp, CDIM, CDIM);
    wtrans_kernel<<<dim3(HID/32,    CDIM/32), 256>>>(fc1_w,  w1, CDIM, HID);
    wtrans_kernel<<<dim3(CDIM/32,   HID/32),  256>>>(fc2_w,  w2, HID,  CDIM);

    // 1. LN1 + shift + window partition (fp16)
    ln1_kernel<<<MTOK, 128>>>(x, norm1_g, norm1_b, win);

    // 2. QKV GEMM (100352 x 384) @ (384 x 1152) -> fp16
    mma_gemm<3><<<dim3(9, MTOK/128), 256, GEMM_SMEM>>>(
        win, wq, qkv_b, nullptr, nullptr, qkvbuf, 3*CDIM, CDIM);

    // 3. Windowed attention (fp16 in, fp16 out)
    attn_kernel<<<dim3(BN, NHEADS), 64>>>(qkvbuf, attnmask, rpb, att);

    // 4. proj GEMM -> fp32
    mma_gemm<0><<<dim3(3, MTOK/128), 256, GEMM_SMEM>>>(
        att, wp, proj_b, nullptr, projb, nullptr, CDIM, CDIM);

    // 5+6. reverse + roll + residual + LN2 (fused)
    mergeln_kernel<<<MTOK, 128>>>(x, projb, norm2_g, norm2_b, y, h2);

    // 7. fc1 + GELU (fp16 out)
    mma_gemm<1><<<dim3(12, MTOK/128), 256, GEMM_SMEM>>>(
        h2, w1, fc1_b, nullptr, nullptr, mlp, HID, CDIM);

    // 8. fc2 + residual -> d_out
    mma_gemm<2><<<dim3(3, MTOK/128), 256, GEMM_SMEM>>>(
        mlp, w2, fc2_b, y, (float*)d_out, nullptr, CDIM, HID);
}